// round 8
// baseline (speedup 1.0000x reference)
#include <cuda_runtime.h>
#include <math.h>

#define NBATCH 2048

// ---- image layout: phase-split, zero halo, conflict-free ----
// row ry = y+2 (0..66), phase ph = xp&3, slot = ph*18 + (xp>>2), xp = x+2 (0..67)
// IMROW = 75: 4*75 = 300 ≡ 12 (mod 32), 12 = 4*3 (3 odd) -> oy(0..7) spans 8 distinct
// 4-aligned bank groups; pr(0..3) fills within group: 32 lanes -> 32 distinct banks.
#define IMROW 75
#define IMCH  (67 * IMROW)          // 5025
#define S_W1  15076                 // conv1 weights [c][ky][f][12] = 3960
#define SMEM_FLOATS (S_W1 + 3960)   // 19036 floats = 76144 bytes -> 3 CTAs/SM

// aliases in the image region (dead after conv1):
#define S_C1   0                    // conv1 out [10][15][16] = 2400
#define S_W2P  2400                 // conv2 weights padded [16][10][5][8] = 6400
#define S_P1P  8800                 // pool1 out zero-padded [10][11][12] = 1320
#define S_C2   10120                // conv2 out [16][4][4] = 256
#define S_FL   10376                // flat 64

__device__ __forceinline__ float leaky(float v) { return v > 0.f ? v : 0.01f * v; }

__device__ __forceinline__ unsigned long long pack2(float lo, float hi) {
    unsigned long long r;
    asm("mov.b64 %0, {%1, %2};" : "=l"(r) : "f"(lo), "f"(hi));
    return r;
}
__device__ __forceinline__ void fma2(unsigned long long& d, unsigned long long a,
                                     unsigned long long b) {
    asm("fma.rn.f32x2 %0, %1, %2, %0;" : "+l"(d) : "l"(a), "l"(b));
}
__device__ __forceinline__ void unpack2(unsigned long long v, float& lo, float& hi) {
    asm("mov.b64 {%0, %1}, %2;" : "=f"(lo), "=f"(hi) : "l"(v));
}

__global__ void __launch_bounds__(256, 3)
cnn_kernel(const float* __restrict__ im,
           const float* __restrict__ w1,
           const float* __restrict__ w2,
           const float* __restrict__ b2,
           const float* __restrict__ lw,
           const float* __restrict__ lb,
           float* __restrict__ out)
{
    extern __shared__ float sm[];
    const int b   = blockIdx.x;
    const int tid = threadIdx.x;

    // ---- zero whole image region (halo correctness), then scatter ----
    for (int i = tid; i < 3 * IMCH; i += 256) sm[i] = 0.f;
    __syncthreads();

    {
        const float2* gim = (const float2*)(im + (size_t)b * 12288);
        for (int i = tid; i < 6144; i += 256) {
            float2 v = gim[i];
            int fi = i << 1;
            int c  = fi >> 12;
            int y  = (fi & 4095) >> 6;
            int x  = fi & 63;
            int base = c * IMCH + (y + 2) * IMROW;
            int xp = x + 2;
            sm[base + (xp & 3) * 18 + (xp >> 2)] = v.x;
            xp++;
            sm[base + (xp & 3) * 18 + (xp >> 2)] = v.y;
        }
    }
    // conv1 weights: [f][c][ky][kx] -> [c][ky][f][12]  (R4-proven layout)
    for (int i = tid; i < 3630; i += 256) {
        int f   = i / 363;
        int rem = i % 363;
        int c   = rem / 121;
        int r2  = rem % 121;
        int ky  = r2 / 11;
        int kx  = r2 % 11;
        sm[S_W1 + ((c * 11 + ky) * 10 + f) * 12 + kx] = w1[i];
    }

    // graph half is analytically constant: softmax == 0.05 (verified exact R1-R7)
    if (tid < 20)
        out[b * 20 + tid] = 0.05f;

    __syncthreads();

    // ---- conv1 (11x11, s4, p2): 15x15 out, ALL 10 filters x 4 pixels per thread ----
    // thread t<60: oy = t>>2 (0..14), pr = t&3
    // pixels: cols {pr, pr+4} (pair0), {pr+8, pr+12} (pair1) as f32x2
    // weight loads are lane-uniform -> full-warp broadcast (1 wavefront each)
    const int oy = tid >> 2, pr = tid & 3;
    const bool c1act = (tid < 60);
    unsigned long long acc[10][2];
    #pragma unroll
    for (int f = 0; f < 10; f++) { acc[f][0] = 0ull; acc[f][1] = 0ull; }

    if (c1act) {
        #pragma unroll 1
        for (int c = 0; c < 3; c++) {
            #pragma unroll 1
            for (int ky = 0; ky < 11; ky++) {
                const float* ip = &sm[c * IMCH + (4 * oy + ky) * IMROW + pr];
                const float* wr = &sm[S_W1 + (c * 11 + ky) * 120];   // + f*12 + k
                #pragma unroll
                for (int k = 0; k < 11; k++) {
                    const int sl = (k & 3) * 18 + (k >> 2);
                    float x0 = ip[sl];
                    float x1 = ip[sl + 4];
                    float x2 = ip[sl + 8];
                    float x3 = ip[sl + 12];   // col pr+12 pad lane when pr==3 (discarded)
                    unsigned long long p01 = pack2(x0, x1);
                    unsigned long long p23 = pack2(x2, x3);
                    #pragma unroll
                    for (int f = 0; f < 10; f++) {
                        float w = wr[f * 12 + k];
                        unsigned long long ww = pack2(w, w);
                        fma2(acc[f][0], p01, ww);
                        fma2(acc[f][1], p23, ww);
                    }
                }
            }
        }
    }
    __syncthreads();   // image reads done; region reusable

    if (c1act) {
        #pragma unroll
        for (int f = 0; f < 10; f++) {
            float v0, v1;
            unpack2(acc[f][0], v0, v1);
            sm[S_C1 + (f * 15 + oy) * 16 + pr]     = leaky(v0);
            sm[S_C1 + (f * 15 + oy) * 16 + pr + 4] = leaky(v1);
            unpack2(acc[f][1], v0, v1);
            sm[S_C1 + (f * 15 + oy) * 16 + pr + 8] = leaky(v0);
            if (pr < 3)
                sm[S_C1 + (f * 15 + oy) * 16 + pr + 12] = leaky(v1);
        }
    }
    // stage conv2 weights padded [f][c][ky][8]
    for (int i = tid; i < 4000; i += 256) {
        int kx = i % 5; int t = i / 5;
        int ky = t % 5; t /= 5;
        int c  = t % 10; int f = t / 10;
        sm[S_W2P + (((f * 10 + c) * 5) + ky) * 8 + kx] = w2[i];
    }
    // zero-fill padded pool1 buffer
    for (int i = tid; i < 1320; i += 256)
        sm[S_P1P + i] = 0.f;
    __syncthreads();

    // ---- maxpool 3x3 s2: 15x15 -> 7x7, write into zero-padded [10][11][12] ----
    for (int i = tid; i < 490; i += 256) {
        int f = i / 49, r = i % 49;
        int py = r / 7, px = r % 7;
        float m = -1e30f;
        #pragma unroll
        for (int dy = 0; dy < 3; dy++)
            #pragma unroll
            for (int dx = 0; dx < 3; dx++)
                m = fmaxf(m, sm[S_C1 + (f * 15 + (2 * py + dy)) * 16 + (2 * px + dx)]);
        sm[S_P1P + (f * 11 + py + 2) * 12 + px + 2] = m;
    }
    __syncthreads();

    // ---- conv2 (5x5, s2, p2): 7x7 -> 4x4, 10 -> 16 ch, guard-free ----
    {
        int f   = tid >> 4;
        int r   = tid & 15;
        int oy2 = r >> 2;
        int ox2 = r & 3;
        float a = b2[f];
        #pragma unroll 1
        for (int c = 0; c < 10; c++) {
            #pragma unroll
            for (int ky = 0; ky < 5; ky++) {
                const float* prow = &sm[S_P1P + (c * 11 + 2 * oy2 + ky) * 12 + 2 * ox2];
                const float4 wv = *(const float4*)&sm[S_W2P + ((f * 10 + c) * 5 + ky) * 8];
                const float  w4 = sm[S_W2P + ((f * 10 + c) * 5 + ky) * 8 + 4];
                a = fmaf(prow[0], wv.x, a);
                a = fmaf(prow[1], wv.y, a);
                a = fmaf(prow[2], wv.z, a);
                a = fmaf(prow[3], wv.w, a);
                a = fmaf(prow[4], w4,  a);
            }
        }
        sm[S_C2 + f * 16 + oy2 * 4 + ox2] = leaky(a);
    }
    __syncthreads();

    // ---- maxpool 2x2 s2: 4x4 -> 2x2, flatten ----
    if (tid < 64) {
        int f = tid >> 2, py = (tid >> 1) & 1, px = tid & 1;
        float m = sm[S_C2 + f * 16 + (2 * py) * 4 + (2 * px)];
        m = fmaxf(m, sm[S_C2 + f * 16 + (2 * py) * 4 + (2 * px + 1)]);
        m = fmaxf(m, sm[S_C2 + f * 16 + (2 * py + 1) * 4 + (2 * px)]);
        m = fmaxf(m, sm[S_C2 + f * 16 + (2 * py + 1) * 4 + (2 * px + 1)]);
        sm[S_FL + tid] = m;   // flat index == tid
    }
    __syncthreads();

    // ---- linear 64 -> 2 + sigmoid ----
    if (tid < 2) {
        float a = lb[tid];
        #pragma unroll
        for (int k = 0; k < 64; k++)
            a = fmaf(sm[S_FL + k], lw[tid * 64 + k], a);
        out[NBATCH * 20 + b * 2 + tid] = 1.f / (1.f + __expf(-a));
    }
}

extern "C" void kernel_launch(void* const* d_in, const int* in_sizes, int n_in,
                              void* d_out, int out_size)
{
    (void)in_sizes; (void)n_in; (void)out_size;
    const float* im = (const float*)d_in[0];
    // d_in[1] = x, d_in[2] = edge_index : dead (graph output is constant 0.05)
    const float* w1 = (const float*)d_in[3];
    const float* w2 = (const float*)d_in[4];
    const float* b2 = (const float*)d_in[5];
    const float* lw = (const float*)d_in[6];
    const float* lb = (const float*)d_in[7];
    float* out = (float*)d_out;

    cudaFuncSetAttribute(cnn_kernel, cudaFuncAttributeMaxDynamicSharedMemorySize,
                         SMEM_FLOATS * sizeof(float));
    cnn_kernel<<<NBATCH, 256, SMEM_FLOATS * sizeof(float)>>>(im, w1, w2, b2, lw, lb, out);
}

// round 9
// speedup vs baseline: 1.3953x; 1.3953x over previous
#include <cuda_runtime.h>
#include <math.h>

#define NBATCH 2048

// ---- image layout: phase-split, zero halo, conflict-free ----
// row ry = y+2 (0..66), phase ph = xp&3, slot = ph*18 + (xp>>2), xp = x+2 (0..67)
#define IMROW 75                    // 4*75 ≡ 12 mod 32 -> oy x pr warp footprint = 32 distinct banks
#define IMCH  (67 * IMROW)          // 5025
#define S_W1  15076                 // conv1 weights [c][ky][f][12] = 3960
#define SMEM_FLOATS (S_W1 + 3960)   // 19036 floats = 76144 bytes -> 3 CTAs/SM

// aliases in the image region (dead after conv1 mainloop):
#define S_TMP  0                    // group-B partial sums [10][15][16] = 2400
#define S_C1   2400                 // conv1 out [10][15][16] = 2400
#define S_W2P  4800                 // conv2 weights padded [16][10][5][8] = 6400
#define S_P1P  11200                // pool1 out zero-padded [10][11][12] = 1320
#define S_C2   12520                // conv2 out [16][4][4] = 256
#define S_FL   12776                // flat 64

__device__ __forceinline__ float leaky(float v) { return v > 0.f ? v : 0.01f * v; }

__global__ void __launch_bounds__(256, 3)
cnn_kernel(const float* __restrict__ im,
           const float* __restrict__ w1,
           const float* __restrict__ w2,
           const float* __restrict__ b2,
           const float* __restrict__ lw,
           const float* __restrict__ lb,
           float* __restrict__ out)
{
    extern __shared__ float sm[];
    const int b   = blockIdx.x;
    const int tid = threadIdx.x;

    // ---- zero whole image region (halo correctness), then scatter ----
    for (int i = tid; i < 3 * IMCH; i += 256) sm[i] = 0.f;
    __syncthreads();

    {
        const float2* gim = (const float2*)(im + (size_t)b * 12288);
        for (int i = tid; i < 6144; i += 256) {
            float2 v = gim[i];
            int fi = i << 1;
            int c  = fi >> 12;
            int y  = (fi & 4095) >> 6;
            int x  = fi & 63;
            int base = c * IMCH + (y + 2) * IMROW;
            int xp = x + 2;
            sm[base + (xp & 3) * 18 + (xp >> 2)] = v.x;
            xp++;
            sm[base + (xp & 3) * 18 + (xp >> 2)] = v.y;
        }
    }
    // conv1 weights: [f][c][ky][kx] -> [c][ky][fh][f'][12]  (f = fh*5 + f', R7 layout)
    for (int i = tid; i < 3630; i += 256) {
        int f   = i / 363;
        int rem = i % 363;
        int c   = rem / 121;
        int r2  = rem % 121;
        int ky  = r2 / 11;
        int kx  = r2 % 11;
        sm[S_W1 + ((((c * 11 + ky) * 2 + (f / 5)) * 5) + (f % 5)) * 12 + kx] = w1[i];
    }

    // graph half is analytically constant: softmax == 0.05 (verified exact R1-R8)
    if (tid < 20)
        out[b * 20 + tid] = 0.05f;

    __syncthreads();

    // ---- conv1 (11x11, s4, p2): 15x15 out, 10 filters ----
    // K-split over reduction rows m = c*11+ky (0..32):
    //   group A = warps 0-3, local id a = tid     (a < 120), rows m in [0,16)
    //   group B = warps 4-7, local id a = tid-128 (a < 120), rows m in [16,33)
    // within group (R7-proven shape): oy = a>>3, pr = (a>>1)&3, fh = a&1
    //   pixels cols {pr, pr+4, pr+8, pr+12}; filters fh*5 .. fh*5+4
    const bool grpB  = (tid >= 128);
    const int  a     = grpB ? (tid - 128) : tid;
    const bool c1act = (a < 120);
    const int  oy = a >> 3, pr = (a >> 1) & 3, fh = a & 1;
    const int  mstart = grpB ? 16 : 0;
    const int  mend   = grpB ? 33 : 16;

    float acc[5][4];
    #pragma unroll
    for (int f = 0; f < 5; f++)
        #pragma unroll
        for (int j = 0; j < 4; j++) acc[f][j] = 0.f;

    if (c1act) {
        #pragma unroll 1
        for (int m = mstart; m < mend; m++) {
            const int c = m / 11, ky = m % 11;
            const float* ip = &sm[c * IMCH + (4 * oy + ky) * IMROW + pr];
            const float* wr = &sm[S_W1 + ((m * 2 + fh) * 5) * 12];
            #pragma unroll
            for (int k = 0; k < 11; k++) {
                const int sl = (k & 3) * 18 + (k >> 2);
                float x0 = ip[sl];
                float x1 = ip[sl + 4];
                float x2 = ip[sl + 8];
                float x3 = ip[sl + 12];   // col pr+12 pad lane when pr==3 (discarded)
                #pragma unroll
                for (int f = 0; f < 5; f++) {
                    float w = wr[f * 12 + k];
                    acc[f][0] = fmaf(x0, w, acc[f][0]);
                    acc[f][1] = fmaf(x1, w, acc[f][1]);
                    acc[f][2] = fmaf(x2, w, acc[f][2]);
                    acc[f][3] = fmaf(x3, w, acc[f][3]);
                }
            }
        }
    }
    __syncthreads();   // image reads done; region reusable

    // group B parks raw partial sums
    if (grpB && c1act) {
        #pragma unroll
        for (int f = 0; f < 5; f++) {
            const int fg = fh * 5 + f;
            #pragma unroll
            for (int j = 0; j < 4; j++) {
                int ox = pr + 4 * j;
                if (ox < 15)
                    sm[S_TMP + (fg * 15 + oy) * 16 + ox] = acc[f][j];
            }
        }
    }
    // stage conv2 weights padded [f][c][ky][8]
    for (int i = tid; i < 4000; i += 256) {
        int kx = i % 5; int t = i / 5;
        int ky = t % 5; t /= 5;
        int c  = t % 10; int f = t / 10;
        sm[S_W2P + (((f * 10 + c) * 5) + ky) * 8 + kx] = w2[i];
    }
    // zero-fill padded pool1 buffer
    for (int i = tid; i < 1320; i += 256)
        sm[S_P1P + i] = 0.f;
    __syncthreads();

    // group A combines partials + leaky -> C1
    if (!grpB && c1act) {
        #pragma unroll
        for (int f = 0; f < 5; f++) {
            const int fg = fh * 5 + f;
            #pragma unroll
            for (int j = 0; j < 4; j++) {
                int ox = pr + 4 * j;
                if (ox < 15) {
                    float v = acc[f][j] + sm[S_TMP + (fg * 15 + oy) * 16 + ox];
                    sm[S_C1 + (fg * 15 + oy) * 16 + ox] = leaky(v);
                }
            }
        }
    }
    __syncthreads();

    // ---- maxpool 3x3 s2: 15x15 -> 7x7, write into zero-padded [10][11][12] ----
    for (int i = tid; i < 490; i += 256) {
        int f = i / 49, r = i % 49;
        int py = r / 7, px = r % 7;
        float m = -1e30f;
        #pragma unroll
        for (int dy = 0; dy < 3; dy++)
            #pragma unroll
            for (int dx = 0; dx < 3; dx++)
                m = fmaxf(m, sm[S_C1 + (f * 15 + (2 * py + dy)) * 16 + (2 * px + dx)]);
        sm[S_P1P + (f * 11 + py + 2) * 12 + px + 2] = m;
    }
    __syncthreads();

    // ---- conv2 (5x5, s2, p2): 7x7 -> 4x4, 10 -> 16 ch, guard-free ----
    {
        int f   = tid >> 4;
        int r   = tid & 15;
        int oy2 = r >> 2;
        int ox2 = r & 3;
        float av = b2[f];
        #pragma unroll 1
        for (int c = 0; c < 10; c++) {
            #pragma unroll
            for (int ky = 0; ky < 5; ky++) {
                const float* prow = &sm[S_P1P + (c * 11 + 2 * oy2 + ky) * 12 + 2 * ox2];
                const float4 wv = *(const float4*)&sm[S_W2P + ((f * 10 + c) * 5 + ky) * 8];
                const float  w4 = sm[S_W2P + ((f * 10 + c) * 5 + ky) * 8 + 4];
                av = fmaf(prow[0], wv.x, av);
                av = fmaf(prow[1], wv.y, av);
                av = fmaf(prow[2], wv.z, av);
                av = fmaf(prow[3], wv.w, av);
                av = fmaf(prow[4], w4,  av);
            }
        }
        sm[S_C2 + f * 16 + oy2 * 4 + ox2] = leaky(av);
    }
    __syncthreads();

    // ---- maxpool 2x2 s2: 4x4 -> 2x2, flatten ----
    if (tid < 64) {
        int f = tid >> 2, py = (tid >> 1) & 1, px = tid & 1;
        float m = sm[S_C2 + f * 16 + (2 * py) * 4 + (2 * px)];
        m = fmaxf(m, sm[S_C2 + f * 16 + (2 * py) * 4 + (2 * px + 1)]);
        m = fmaxf(m, sm[S_C2 + f * 16 + (2 * py + 1) * 4 + (2 * px)]);
        m = fmaxf(m, sm[S_C2 + f * 16 + (2 * py + 1) * 4 + (2 * px + 1)]);
        sm[S_FL + tid] = m;   // flat index == tid
    }
    __syncthreads();

    // ---- linear 64 -> 2 + sigmoid ----
    if (tid < 2) {
        float a2 = lb[tid];
        #pragma unroll
        for (int k = 0; k < 64; k++)
            a2 = fmaf(sm[S_FL + k], lw[tid * 64 + k], a2);
        out[NBATCH * 20 + b * 2 + tid] = 1.f / (1.f + __expf(-a2));
    }
}

extern "C" void kernel_launch(void* const* d_in, const int* in_sizes, int n_in,
                              void* d_out, int out_size)
{
    (void)in_sizes; (void)n_in; (void)out_size;
    const float* im = (const float*)d_in[0];
    // d_in[1] = x, d_in[2] = edge_index : dead (graph output is constant 0.05)
    const float* w1 = (const float*)d_in[3];
    const float* w2 = (const float*)d_in[4];
    const float* b2 = (const float*)d_in[5];
    const float* lw = (const float*)d_in[6];
    const float* lb = (const float*)d_in[7];
    float* out = (float*)d_out;

    cudaFuncSetAttribute(cnn_kernel, cudaFuncAttributeMaxDynamicSharedMemorySize,
                         SMEM_FLOATS * sizeof(float));
    cnn_kernel<<<NBATCH, 256, SMEM_FLOATS * sizeof(float)>>>(im, w1, w2, b2, lw, lb, out);
}

// round 10
// speedup vs baseline: 1.5003x; 1.0753x over previous
#include <cuda_runtime.h>
#include <math.h>

#define NBATCH 2048

// ---- image layout: plain rows, stride 68, x stored at idx x+2 ----
// row ry = y+2 (0..66, rows 0,1,66 zero), idx 0,1,66,67 zero pad
// pixel ox window: k=0..10 -> idx 4*ox .. 4*ox+10 (16B-aligned base)
#define IMROW 68
#define IMCH  (67 * IMROW)          // 4556
#define S_W1  13668                 // conv1 weights [c][ky][f][12] = 3960 (float4-aligned)
#define SMEM_FLOATS (S_W1 + 3960)   // 17628 floats = 70512 bytes -> 3 CTAs/SM

// aliases in the image region (dead after conv1):
#define S_C1   0                    // conv1 out [10][15][16] = 2400
#define S_W2P  2400                 // conv2 weights padded [16][10][5][8] = 6400
#define S_P1P  8800                 // pool1 out zero-padded [10][11][12] = 1320
#define S_C2   10120                // conv2 out [16][4][4] = 256
#define S_FL   10376                // flat 64

__device__ __forceinline__ float leaky(float v) { return v > 0.f ? v : 0.01f * v; }

__global__ void __launch_bounds__(256, 3)
cnn_kernel(const float* __restrict__ im,
           const float* __restrict__ w1,
           const float* __restrict__ w2,
           const float* __restrict__ b2,
           const float* __restrict__ lw,
           const float* __restrict__ lb,
           float* __restrict__ out)
{
    extern __shared__ float sm[];
    const int b   = blockIdx.x;
    const int tid = threadIdx.x;

    // ---- zero image + weight regions (halo & pad-lane correctness) ----
    for (int i = tid; i < SMEM_FLOATS; i += 256) sm[i] = 0.f;
    __syncthreads();

    {
        const float2* gim = (const float2*)(im + (size_t)b * 12288);
        for (int i = tid; i < 6144; i += 256) {
            float2 v = gim[i];
            int fi = i << 1;
            int c  = fi >> 12;
            int y  = (fi & 4095) >> 6;
            int x  = fi & 63;
            int base = c * IMCH + (y + 2) * IMROW + x + 2;
            sm[base]     = v.x;
            sm[base + 1] = v.y;
        }
    }
    // conv1 weights: [f][c][ky][kx] -> [c][ky][f][12] (pad lane kx=11 stays 0)
    for (int i = tid; i < 3630; i += 256) {
        int f   = i / 363;
        int rem = i % 363;
        int c   = rem / 121;
        int r2  = rem % 121;
        int ky  = r2 / 11;
        int kx  = r2 % 11;
        sm[S_W1 + ((c * 11 + ky) * 10 + f) * 12 + kx] = w1[i];
    }

    // graph half is analytically constant: softmax == 0.05 (verified exact R1-R9)
    if (tid < 20)
        out[b * 20 + tid] = 0.05f;

    __syncthreads();

    // ---- conv1 (11x11, s4, p2): 15x15 out, 10 filters ----
    // thread a<120: oy = a>>3 (0..14), pr = (a>>1)&3, fh = a&1
    // pixels ox in {pr, pr+4, pr+8, pr+12}; filters fh*5 .. fh*5+4
    // all operand loads are LDS.128: 4 input + 5 weight float4 per k-chunk q
    const int oy = tid >> 3, pr = (tid >> 1) & 3, fh = tid & 1;
    const bool c1act = (tid < 120);
    float acc[5][4];
    #pragma unroll
    for (int f = 0; f < 5; f++)
        #pragma unroll
        for (int j = 0; j < 4; j++) acc[f][j] = 0.f;

    if (c1act) {
        #pragma unroll 1
        for (int c = 0; c < 3; c++) {
            #pragma unroll 1
            for (int ky = 0; ky < 11; ky++) {
                // float4 row base; pixel ox=pr+4j chunk q at float4 idx pr+4j+q
                const float4* ip = (const float4*)&sm[c * IMCH + (4 * oy + ky) * IMROW];
                const float4* wp = (const float4*)&sm[S_W1 + ((c * 11 + ky) * 10 + fh * 5) * 12];
                #pragma unroll
                for (int q = 0; q < 3; q++) {
                    float4 in0 = ip[pr + 0  + q];
                    float4 in1 = ip[pr + 4  + q];
                    float4 in2 = ip[pr + 8  + q];
                    float4 in3 = ip[pr + 12 + q];   // ox=15 lane: garbage, discarded
                    #pragma unroll
                    for (int f = 0; f < 5; f++) {
                        float4 w = wp[f * 3 + q];
                        acc[f][0] = fmaf(in0.x, w.x, acc[f][0]);
                        acc[f][0] = fmaf(in0.y, w.y, acc[f][0]);
                        acc[f][0] = fmaf(in0.z, w.z, acc[f][0]);
                        acc[f][0] = fmaf(in0.w, w.w, acc[f][0]);
                        acc[f][1] = fmaf(in1.x, w.x, acc[f][1]);
                        acc[f][1] = fmaf(in1.y, w.y, acc[f][1]);
                        acc[f][1] = fmaf(in1.z, w.z, acc[f][1]);
                        acc[f][1] = fmaf(in1.w, w.w, acc[f][1]);
                        acc[f][2] = fmaf(in2.x, w.x, acc[f][2]);
                        acc[f][2] = fmaf(in2.y, w.y, acc[f][2]);
                        acc[f][2] = fmaf(in2.z, w.z, acc[f][2]);
                        acc[f][2] = fmaf(in2.w, w.w, acc[f][2]);
                        acc[f][3] = fmaf(in3.x, w.x, acc[f][3]);
                        acc[f][3] = fmaf(in3.y, w.y, acc[f][3]);
                        acc[f][3] = fmaf(in3.z, w.z, acc[f][3]);
                        acc[f][3] = fmaf(in3.w, w.w, acc[f][3]);
                    }
                }
            }
        }
    }
    __syncthreads();   // image reads done; region reusable

    if (c1act) {
        #pragma unroll
        for (int f = 0; f < 5; f++) {
            const int fg = fh * 5 + f;
            #pragma unroll
            for (int j = 0; j < 4; j++) {
                int ox = pr + 4 * j;
                if (ox < 15)
                    sm[S_C1 + (fg * 15 + oy) * 16 + ox] = leaky(acc[f][j]);
            }
        }
    }
    // stage conv2 weights padded [f][c][ky][8]
    for (int i = tid; i < 4000; i += 256) {
        int kx = i % 5; int t = i / 5;
        int ky = t % 5; t /= 5;
        int c  = t % 10; int f = t / 10;
        sm[S_W2P + (((f * 10 + c) * 5) + ky) * 8 + kx] = w2[i];
    }
    // zero-fill padded pool1 buffer
    for (int i = tid; i < 1320; i += 256)
        sm[S_P1P + i] = 0.f;
    __syncthreads();

    // ---- maxpool 3x3 s2: 15x15 -> 7x7, write into zero-padded [10][11][12] ----
    for (int i = tid; i < 490; i += 256) {
        int f = i / 49, r = i % 49;
        int py = r / 7, px = r % 7;
        float m = -1e30f;
        #pragma unroll
        for (int dy = 0; dy < 3; dy++)
            #pragma unroll
            for (int dx = 0; dx < 3; dx++)
                m = fmaxf(m, sm[S_C1 + (f * 15 + (2 * py + dy)) * 16 + (2 * px + dx)]);
        sm[S_P1P + (f * 11 + py + 2) * 12 + px + 2] = m;
    }
    __syncthreads();

    // ---- conv2 (5x5, s2, p2): 7x7 -> 4x4, 10 -> 16 ch, guard-free ----
    {
        int f   = tid >> 4;
        int r   = tid & 15;
        int oy2 = r >> 2;
        int ox2 = r & 3;
        float av = b2[f];
        #pragma unroll 1
        for (int c = 0; c < 10; c++) {
            #pragma unroll
            for (int ky = 0; ky < 5; ky++) {
                const float* prow = &sm[S_P1P + (c * 11 + 2 * oy2 + ky) * 12 + 2 * ox2];
                const float4 wv = *(const float4*)&sm[S_W2P + ((f * 10 + c) * 5 + ky) * 8];
                const float  w4 = sm[S_W2P + ((f * 10 + c) * 5 + ky) * 8 + 4];
                av = fmaf(prow[0], wv.x, av);
                av = fmaf(prow[1], wv.y, av);
                av = fmaf(prow[2], wv.z, av);
                av = fmaf(prow[3], wv.w, av);
                av = fmaf(prow[4], w4,  av);
            }
        }
        sm[S_C2 + f * 16 + oy2 * 4 + ox2] = leaky(av);
    }
    __syncthreads();

    // ---- maxpool 2x2 s2: 4x4 -> 2x2, flatten ----
    if (tid < 64) {
        int f = tid >> 2, py = (tid >> 1) & 1, px = tid & 1;
        float m = sm[S_C2 + f * 16 + (2 * py) * 4 + (2 * px)];
        m = fmaxf(m, sm[S_C2 + f * 16 + (2 * py) * 4 + (2 * px + 1)]);
        m = fmaxf(m, sm[S_C2 + f * 16 + (2 * py + 1) * 4 + (2 * px)]);
        m = fmaxf(m, sm[S_C2 + f * 16 + (2 * py + 1) * 4 + (2 * px + 1)]);
        sm[S_FL + tid] = m;   // flat index == tid
    }
    __syncthreads();

    // ---- linear 64 -> 2 + sigmoid ----
    if (tid < 2) {
        float a2 = lb[tid];
        #pragma unroll
        for (int k = 0; k < 64; k++)
            a2 = fmaf(sm[S_FL + k], lw[tid * 64 + k], a2);
        out[NBATCH * 20 + b * 2 + tid] = 1.f / (1.f + __expf(-a2));
    }
}

extern "C" void kernel_launch(void* const* d_in, const int* in_sizes, int n_in,
                              void* d_out, int out_size)
{
    (void)in_sizes; (void)n_in; (void)out_size;
    const float* im = (const float*)d_in[0];
    // d_in[1] = x, d_in[2] = edge_index : dead (graph output is constant 0.05)
    const float* w1 = (const float*)d_in[3];
    const float* w2 = (const float*)d_in[4];
    const float* b2 = (const float*)d_in[5];
    const float* lw = (const float*)d_in[6];
    const float* lb = (const float*)d_in[7];
    float* out = (float*)d_out;

    cudaFuncSetAttribute(cnn_kernel, cudaFuncAttributeMaxDynamicSharedMemorySize,
                         SMEM_FLOATS * sizeof(float));
    cnn_kernel<<<NBATCH, 256, SMEM_FLOATS * sizeof(float)>>>(im, w1, w2, b2, lw, lb, out);
}

// round 11
// speedup vs baseline: 1.5426x; 1.0282x over previous
#include <cuda_runtime.h>
#include <math.h>

#define NBATCH 2048

// ---- image layout: plain rows, stride 68 (=17 float4), x stored at idx x+2 ----
// row ry = y+2 (0..66, rows 0,1,66 zero), idx 0,1,66,67 zero pad
// pixel ox: taps = floats 4*ox .. 4*ox+10
#define IMROW 68
#define IMCH  (67 * IMROW)          // 4556 (mult of 4 -> float4-aligned rows)
#define S_W1  13668                 // conv1 weights [c][ky][f][12] = 3960 (float4-aligned)
#define SMEM_FLOATS (S_W1 + 3960)   // 17628 floats = 70512 bytes -> 3 CTAs/SM

// aliases in the image region (dead after conv1):
#define S_C1   0                    // conv1 out [10][15][16] = 2400
#define S_W2P  2400                 // conv2 weights padded [16][10][5][8] = 6400
#define S_P1P  8800                 // pool1 out zero-padded [10][11][12] = 1320
#define S_C2   10120                // conv2 out [16][4][4] = 256
#define S_FL   10376                // flat 64

__device__ __forceinline__ float leaky(float v) { return v > 0.f ? v : 0.01f * v; }

__global__ void __launch_bounds__(256, 3)
cnn_kernel(const float* __restrict__ im,
           const float* __restrict__ w1,
           const float* __restrict__ w2,
           const float* __restrict__ b2,
           const float* __restrict__ lw,
           const float* __restrict__ lb,
           float* __restrict__ out)
{
    extern __shared__ float sm[];
    const int b   = blockIdx.x;
    const int tid = threadIdx.x;

    // ---- zero image + weight regions (halo & pad-lane correctness) ----
    for (int i = tid; i < SMEM_FLOATS; i += 256) sm[i] = 0.f;
    __syncthreads();

    {
        const float2* gim = (const float2*)(im + (size_t)b * 12288);
        for (int i = tid; i < 6144; i += 256) {
            float2 v = gim[i];
            int fi = i << 1;
            int c  = fi >> 12;
            int y  = (fi & 4095) >> 6;
            int x  = fi & 63;
            int base = c * IMCH + (y + 2) * IMROW + x + 2;
            sm[base]     = v.x;
            sm[base + 1] = v.y;
        }
    }
    // conv1 weights: [f][c][ky][kx] -> [c][ky][f][12] (pad lane kx=11 stays 0)
    for (int i = tid; i < 3630; i += 256) {
        int f   = i / 363;
        int rem = i % 363;
        int c   = rem / 121;
        int r2  = rem % 121;
        int ky  = r2 / 11;
        int kx  = r2 % 11;
        sm[S_W1 + ((c * 11 + ky) * 10 + f) * 12 + kx] = w1[i];
    }

    // graph half is analytically constant: softmax == 0.05 (verified exact R1-R10)
    if (tid < 20)
        out[b * 20 + tid] = 0.05f;

    __syncthreads();

    // ---- conv1 (11x11, s4, p2): 15x15 out, 10 filters ----
    // thread a<120: oy = a>>3 (0..14), pr = (a>>1)&3, fh = a&1
    // ADJACENT pixels ox = 4*pr + d, d=0..3: windows overlap -> one row needs
    // only 6 input float4s (idx 4pr .. 4pr+5); taps register-indexed.
    // filters fh*5 .. fh*5+4; per row: 6 input + 15 weight LDS.128, 220 FMA.
    const int oy = tid >> 3, pr = (tid >> 1) & 3, fh = tid & 1;
    const bool c1act = (tid < 120);
    float acc[5][4];
    #pragma unroll
    for (int f = 0; f < 5; f++)
        #pragma unroll
        for (int j = 0; j < 4; j++) acc[f][j] = 0.f;

    if (c1act) {
        #pragma unroll 1
        for (int c = 0; c < 3; c++) {
            // row base as float4: (c*IMCH + (4*oy+ky)*IMROW)/4 + 4*pr ; row = 17 float4
            const float4* rp = (const float4*)&sm[c * IMCH + (4 * oy) * IMROW] + 4 * pr;
            const float*  wb = &sm[S_W1 + (c * 11) * 120 + fh * 60];  // + ky*120 + f*12
            #pragma unroll 2
            for (int ky = 0; ky < 11; ky++) {
                float4 X[6];
                const float4* row = rp + ky * 17;
                #pragma unroll
                for (int i = 0; i < 6; i++) X[i] = row[i];
                const float* xs = (const float*)X;   // 24 floats, pixel d taps xs[4d+k]
                const float* wr = wb + ky * 120;
                #pragma unroll
                for (int f = 0; f < 5; f++) {
                    float4 wa = *(const float4*)(wr + f * 12);
                    float4 wv = *(const float4*)(wr + f * 12 + 4);
                    float4 wc = *(const float4*)(wr + f * 12 + 8);
                    float w[11] = {wa.x, wa.y, wa.z, wa.w,
                                   wv.x, wv.y, wv.z, wv.w,
                                   wc.x, wc.y, wc.z};
                    #pragma unroll
                    for (int d = 0; d < 4; d++) {
                        float a = acc[f][d];
                        #pragma unroll
                        for (int k = 0; k < 11; k++)
                            a = fmaf(xs[4 * d + k], w[k], a);
                        acc[f][d] = a;
                    }
                }
            }
        }
    }
    __syncthreads();   // image reads done; region reusable

    if (c1act) {
        #pragma unroll
        for (int f = 0; f < 5; f++) {
            const int fg = fh * 5 + f;
            #pragma unroll
            for (int d = 0; d < 4; d++) {
                int ox = 4 * pr + d;
                if (ox < 15)
                    sm[S_C1 + (fg * 15 + oy) * 16 + ox] = leaky(acc[f][d]);
            }
        }
    }
    // stage conv2 weights padded [f][c][ky][8]
    for (int i = tid; i < 4000; i += 256) {
        int kx = i % 5; int t = i / 5;
        int ky = t % 5; t /= 5;
        int c  = t % 10; int f = t / 10;
        sm[S_W2P + (((f * 10 + c) * 5) + ky) * 8 + kx] = w2[i];
    }
    // zero-fill padded pool1 buffer
    for (int i = tid; i < 1320; i += 256)
        sm[S_P1P + i] = 0.f;
    __syncthreads();

    // ---- maxpool 3x3 s2: 15x15 -> 7x7, write into zero-padded [10][11][12] ----
    for (int i = tid; i < 490; i += 256) {
        int f = i / 49, r = i % 49;
        int py = r / 7, px = r % 7;
        float m = -1e30f;
        #pragma unroll
        for (int dy = 0; dy < 3; dy++)
            #pragma unroll
            for (int dx = 0; dx < 3; dx++)
                m = fmaxf(m, sm[S_C1 + (f * 15 + (2 * py + dy)) * 16 + (2 * px + dx)]);
        sm[S_P1P + (f * 11 + py + 2) * 12 + px + 2] = m;
    }
    __syncthreads();

    // ---- conv2 (5x5, s2, p2): 7x7 -> 4x4, 10 -> 16 ch, guard-free ----
    {
        int f   = tid >> 4;
        int r   = tid & 15;
        int oy2 = r >> 2;
        int ox2 = r & 3;
        float av = b2[f];
        #pragma unroll 1
        for (int c = 0; c < 10; c++) {
            #pragma unroll
            for (int ky = 0; ky < 5; ky++) {
                const float* prow = &sm[S_P1P + (c * 11 + 2 * oy2 + ky) * 12 + 2 * ox2];
                const float4 wv = *(const float4*)&sm[S_W2P + ((f * 10 + c) * 5 + ky) * 8];
                const float  w4 = sm[S_W2P + ((f * 10 + c) * 5 + ky) * 8 + 4];
                av = fmaf(prow[0], wv.x, av);
                av = fmaf(prow[1], wv.y, av);
                av = fmaf(prow[2], wv.z, av);
                av = fmaf(prow[3], wv.w, av);
                av = fmaf(prow[4], w4,  av);
            }
        }
        sm[S_C2 + f * 16 + oy2 * 4 + ox2] = leaky(av);
    }
    __syncthreads();

    // ---- maxpool 2x2 s2: 4x4 -> 2x2, flatten ----
    if (tid < 64) {
        int f = tid >> 2, py = (tid >> 1) & 1, px = tid & 1;
        float m = sm[S_C2 + f * 16 + (2 * py) * 4 + (2 * px)];
        m = fmaxf(m, sm[S_C2 + f * 16 + (2 * py) * 4 + (2 * px + 1)]);
        m = fmaxf(m, sm[S_C2 + f * 16 + (2 * py + 1) * 4 + (2 * px)]);
        m = fmaxf(m, sm[S_C2 + f * 16 + (2 * py + 1) * 4 + (2 * px + 1)]);
        sm[S_FL + tid] = m;   // flat index == tid
    }
    __syncthreads();

    // ---- linear 64 -> 2 + sigmoid ----
    if (tid < 2) {
        float a2 = lb[tid];
        #pragma unroll
        for (int k = 0; k < 64; k++)
            a2 = fmaf(sm[S_FL + k], lw[tid * 64 + k], a2);
        out[NBATCH * 20 + b * 2 + tid] = 1.f / (1.f + __expf(-a2));
    }
}

extern "C" void kernel_launch(void* const* d_in, const int* in_sizes, int n_in,
                              void* d_out, int out_size)
{
    (void)in_sizes; (void)n_in; (void)out_size;
    const float* im = (const float*)d_in[0];
    // d_in[1] = x, d_in[2] = edge_index : dead (graph output is constant 0.05)
    const float* w1 = (const float*)d_in[3];
    const float* w2 = (const float*)d_in[4];
    const float* b2 = (const float*)d_in[5];
    const float* lw = (const float*)d_in[6];
    const float* lb = (const float*)d_in[7];
    float* out = (float*)d_out;

    cudaFuncSetAttribute(cnn_kernel, cudaFuncAttributeMaxDynamicSharedMemorySize,
                         SMEM_FLOATS * sizeof(float));
    cnn_kernel<<<NBATCH, 256, SMEM_FLOATS * sizeof(float)>>>(im, w1, w2, b2, lw, lb, out);
}